// round 3
// baseline (speedup 1.0000x reference)
#include <cuda_runtime.h>
#include <cuda_fp16.h>
#include <cstdint>

#define DI __device__ __forceinline__

// ---------------- problem constants ----------------
static constexpr int M_TOTAL = 8192;
static constexpr int N_TOTAL = 4096;
static constexpr int K_TOTAL = 4096;

static constexpr int TILE_M = 128;
static constexpr int TILE_N = 256;
static constexpr int TILE_K = 64;                     // 64 fp16 = 128B rows (SW128 atom)
static constexpr int NUM_CHUNKS = K_TOTAL / TILE_K;   // 64
static constexpr int STAGES = 3;

static constexpr int A_BYTES = TILE_M * 128;          // 16 KB
static constexpr int B_BYTES = TILE_N * 128;          // 32 KB
static constexpr int STAGE_BYTES = A_BYTES + B_BYTES; // 48 KB
static constexpr int SMEM_ALLOC = STAGES * STAGE_BYTES + 256;

// ---------------- scratch (no cudaMalloc allowed) ----------------
__device__ __align__(16) __half g_W[(size_t)N_TOTAL * K_TOTAL]; // [n][k] K-major, 32 MB
__device__ __align__(16) __half g_X[(size_t)M_TOTAL * K_TOTAL]; // [m][k] K-major, 64 MB

__device__ const float c_nf4[16] = {
    -1.0f, -0.6961928009986877f, -0.5250730514526367f, -0.39491748809814453f,
    -0.28444138169288635f, -0.18477343022823334f, -0.09105003625154495f, 0.0f,
    0.07958029955625534f, 0.16093020141124725f, 0.24611230194568634f,
    0.33791524171829224f, 0.44070982933044434f, 0.5626170039176941f,
    0.7229568362236023f, 1.0f};

// ---------------- PTX helpers (all base-sm_103 legal) ----------------
DI uint32_t smem_u32(const void* p) {
    return (uint32_t)__cvta_generic_to_shared(p);
}
DI void cp_async16(uint32_t dst, const void* src) {
    asm volatile("cp.async.cg.shared.global [%0], [%1], 16;\n" :: "r"(dst), "l"(src));
}
DI void cp_async_commit() { asm volatile("cp.async.commit_group;\n" ::: "memory"); }
template <int N>
DI void cp_async_wait() { asm volatile("cp.async.wait_group %0;\n" :: "n"(N) : "memory"); }

DI void ldmatrix_x4(uint32_t& r0, uint32_t& r1, uint32_t& r2, uint32_t& r3, uint32_t addr) {
    asm volatile("ldmatrix.sync.aligned.m8n8.x4.shared.b16 {%0,%1,%2,%3}, [%4];"
                 : "=r"(r0), "=r"(r1), "=r"(r2), "=r"(r3) : "r"(addr));
}
DI void mma_16816(float& d0, float& d1, float& d2, float& d3,
                  uint32_t a0, uint32_t a1, uint32_t a2, uint32_t a3,
                  uint32_t b0, uint32_t b1) {
    asm volatile(
        "mma.sync.aligned.m16n8k16.row.col.f32.f16.f16.f32 "
        "{%0,%1,%2,%3}, {%4,%5,%6,%7}, {%8,%9}, {%0,%1,%2,%3};"
        : "+f"(d0), "+f"(d1), "+f"(d2), "+f"(d3)
        : "r"(a0), "r"(a1), "r"(a2), "r"(a3), "r"(b0), "r"(b1));
}

// ---------------- kernel 1: dequant qweight -> g_W[n][k] fp16 ----------------
__global__ void __launch_bounds__(256) dequant_kernel(const int* __restrict__ qw,
                                                      const float* __restrict__ scales) {
    int gid = blockIdx.x * 256 + threadIdx.x;   // over (K/8)*N = 2,097,152
    int r = gid >> 12;                          // qweight row (k = r*8 + j)
    int n = gid & (N_TOTAL - 1);
    uint32_t q = (uint32_t)qw[gid];
    float s = scales[(r >> 4) * N_TOTAL + n];   // group = (r*8)/128 = r/16
    uint4 pack;
    __half* h = reinterpret_cast<__half*>(&pack);
#pragma unroll
    for (int j = 0; j < 8; j++)
        h[j] = __float2half_rn(c_nf4[(q >> (4 * j)) & 15] * s);
    *reinterpret_cast<uint4*>(&g_W[(size_t)n * K_TOTAL + (size_t)r * 8]) = pack;
}

// ---------------- kernel 2: x fp32 -> g_X fp16 ----------------
__global__ void __launch_bounds__(256) xconv_kernel(const float* __restrict__ x) {
    size_t gid = (size_t)blockIdx.x * 256 + threadIdx.x;  // over M*K/8
    const float4* src = reinterpret_cast<const float4*>(x) + gid * 2;
    float4 a = src[0];
    float4 b = src[1];
    uint4 pack;
    __half* h = reinterpret_cast<__half*>(&pack);
    h[0] = __float2half_rn(a.x); h[1] = __float2half_rn(a.y);
    h[2] = __float2half_rn(a.z); h[3] = __float2half_rn(a.w);
    h[4] = __float2half_rn(b.x); h[5] = __float2half_rn(b.y);
    h[6] = __float2half_rn(b.z); h[7] = __float2half_rn(b.w);
    *reinterpret_cast<uint4*>(&g_X[gid * 8]) = pack;
}

// ---------------- kernel 3: HMMA fp16 GEMM + bias ----------------
// CTA 128x256x(K=64/stage), 3-stage cp.async pipeline, 8 warps in 2(M) x 4(N),
// warp tile 64x64 -> per warp 4x8 m16n8 tiles, fp32 accum.
__global__ void __launch_bounds__(256, 1) gemm_kernel(const float* __restrict__ bias,
                                                      float* __restrict__ out) {
    extern __shared__ char dyn_smem[];
    const int tid = threadIdx.x;
    const int wid = tid >> 5;
    const int lid = tid & 31;
    const int warp_m = wid & 1;    // 0..1
    const int warp_n = wid >> 1;   // 0..3
    const int n_tile = blockIdx.x;
    const int m_tile = blockIdx.y;

    uint32_t smem_base = (smem_u32(dyn_smem) + 127u) & ~127u;

    const char* gA = reinterpret_cast<const char*>(g_X) +
                     (size_t)(m_tile * TILE_M) * (K_TOTAL * 2);
    const char* gB = reinterpret_cast<const char*>(g_W) +
                     (size_t)(n_tile * TILE_N) * (K_TOTAL * 2);

    // ---- cp.async mapping: 16B granules, 8 per 128B row ----
    const int gcol = tid & 7;          // chunk 0..7 within row
    const int grow = tid >> 3;         // 0..31
    const uint32_t dst_chunk = (uint32_t)(gcol ^ (grow & 7)) << 4;  // swizzled slot

    auto load_stage = [&](int buf, int c) {
        const uint32_t sA = smem_base + buf * STAGE_BYTES;
        const uint32_t sB = sA + A_BYTES;
        const size_t koff = (size_t)c * 128 + gcol * 16;
#pragma unroll
        for (int j = 0; j < 4; j++) {           // A: 128 rows
            int row = grow + 32 * j;
            cp_async16(sA + row * 128 + dst_chunk,
                       gA + (size_t)row * (K_TOTAL * 2) + koff);
        }
#pragma unroll
        for (int j = 0; j < 8; j++) {           // B: 256 rows
            int row = grow + 32 * j;
            cp_async16(sB + row * 128 + dst_chunk,
                       gB + (size_t)row * (K_TOTAL * 2) + koff);
        }
    };

    // prologue: 2 stages in flight
    load_stage(0, 0);
    cp_async_commit();
    load_stage(1, 1);
    cp_async_commit();

    // ---- ldmatrix lane addressing (SW128: chunk' = chunk ^ (row&7)) ----
    const int lrow = lid & 15;                     // row within 16-row group
    const uint32_t lchunk = (uint32_t)(lid >> 4);  // 0/1: k-halves
    const uint32_t lxor = (uint32_t)(lid & 7);
    const uint32_t rowA = (uint32_t)(warp_m * 64 + lrow) * 128;
    const uint32_t rowB = (uint32_t)(warp_n * 64 + lrow) * 128;

    float acc[4][8][4];
#pragma unroll
    for (int mi = 0; mi < 4; mi++)
#pragma unroll
        for (int ni = 0; ni < 8; ni++)
#pragma unroll
            for (int v = 0; v < 4; v++) acc[mi][ni][v] = 0.0f;

    for (int c = 0; c < NUM_CHUNKS; c++) {
        cp_async_wait<1>();   // stage c resident
        __syncthreads();      // visible to all; prior readers of buf (c+2)%3 done

        const int nc = c + STAGES - 1;
        if (nc < NUM_CHUNKS) load_stage(nc % STAGES, nc);
        cp_async_commit();

        const uint32_t sA = smem_base + (c % STAGES) * STAGE_BYTES;
        const uint32_t sB = sA + A_BYTES;

#pragma unroll
        for (int ks = 0; ks < 4; ks++) {
            const uint32_t csw = (((uint32_t)(2 * ks) + lchunk) ^ lxor) << 4;
            uint32_t a[4][4], b[4][4];
#pragma unroll
            for (int mi = 0; mi < 4; mi++)
                ldmatrix_x4(a[mi][0], a[mi][1], a[mi][2], a[mi][3],
                            sA + rowA + mi * 16 * 128 + csw);
#pragma unroll
            for (int nj = 0; nj < 4; nj++)
                ldmatrix_x4(b[nj][0], b[nj][1], b[nj][2], b[nj][3],
                            sB + rowB + nj * 16 * 128 + csw);
#pragma unroll
            for (int mi = 0; mi < 4; mi++) {
#pragma unroll
                for (int nj = 0; nj < 4; nj++) {
                    mma_16816(acc[mi][2 * nj][0], acc[mi][2 * nj][1],
                              acc[mi][2 * nj][2], acc[mi][2 * nj][3],
                              a[mi][0], a[mi][1], a[mi][2], a[mi][3],
                              b[nj][0], b[nj][2]);
                    mma_16816(acc[mi][2 * nj + 1][0], acc[mi][2 * nj + 1][1],
                              acc[mi][2 * nj + 1][2], acc[mi][2 * nj + 1][3],
                              a[mi][0], a[mi][1], a[mi][2], a[mi][3],
                              b[nj][1], b[nj][3]);
                }
            }
        }
    }

    // ---- epilogue: add bias, write fp32 out ----
    const int qr = lid >> 2;          // 0..7
    const int qc = (lid & 3) * 2;
    const int m_base = m_tile * TILE_M + warp_m * 64;
    const int n_base = n_tile * TILE_N + warp_n * 64;

#pragma unroll
    for (int ni = 0; ni < 8; ni++) {
        const int col = n_base + ni * 8 + qc;
        const float2 bv = *reinterpret_cast<const float2*>(bias + col);
#pragma unroll
        for (int mi = 0; mi < 4; mi++) {
            const int r0 = m_base + mi * 16 + qr;
            float2 v0, v1;
            v0.x = acc[mi][ni][0] + bv.x;
            v0.y = acc[mi][ni][1] + bv.y;
            v1.x = acc[mi][ni][2] + bv.x;
            v1.y = acc[mi][ni][3] + bv.y;
            *reinterpret_cast<float2*>(out + (size_t)r0 * N_TOTAL + col) = v0;
            *reinterpret_cast<float2*>(out + (size_t)(r0 + 8) * N_TOTAL + col) = v1;
        }
    }
}

// ---------------- launch ----------------
extern "C" void kernel_launch(void* const* d_in, const int* in_sizes, int n_in,
                              void* d_out, int out_size) {
    const float* x      = (const float*)d_in[0];
    const float* scales = (const float*)d_in[1];
    const float* bias   = (const float*)d_in[2];
    const int*   qw     = (const int*)d_in[3];
    float* out = (float*)d_out;

    cudaFuncSetAttribute(gemm_kernel,
                         cudaFuncAttributeMaxDynamicSharedMemorySize, SMEM_ALLOC);

    dequant_kernel<<<(K_TOTAL / 8) * N_TOTAL / 256, 256>>>(qw, scales);
    xconv_kernel<<<(int)((size_t)M_TOTAL * K_TOTAL / 8 / 256), 256>>>(x);

    dim3 grid(N_TOTAL / TILE_N, M_TOTAL / TILE_M);   // 16 x 64
    gemm_kernel<<<grid, 256, SMEM_ALLOC>>>(bias, out);
}

// round 9
// speedup vs baseline: 1.0147x; 1.0147x over previous
#include <cuda_runtime.h>
#include <cuda_fp16.h>
#include <cstdint>

#define DI __device__ __forceinline__

// ---------------- problem constants ----------------
static constexpr int M_TOTAL = 8192;
static constexpr int N_TOTAL = 4096;
static constexpr int K_TOTAL = 4096;

static constexpr int TILE_M = 128;
static constexpr int TILE_N = 256;
static constexpr int TILE_K = 64;                     // 64 fp16 = 128B rows (SW128 atom)
static constexpr int NUM_CHUNKS = K_TOTAL / TILE_K;   // 64
static constexpr int STAGES = 4;                      // 4-deep cp.async ring

static constexpr int A_BYTES = TILE_M * 128;          // 16 KB
static constexpr int B_BYTES = TILE_N * 128;          // 32 KB
static constexpr int STAGE_BYTES = A_BYTES + B_BYTES; // 48 KB
static constexpr int SMEM_ALLOC = STAGES * STAGE_BYTES + 256;   // ~192 KB

// ---------------- scratch (no cudaMalloc allowed) ----------------
__device__ __align__(16) __half g_W[(size_t)N_TOTAL * K_TOTAL]; // [n][k] K-major, 32 MB
__device__ __align__(16) __half g_X[(size_t)M_TOTAL * K_TOTAL]; // [m][k] K-major, 64 MB

__device__ const float c_nf4[16] = {
    -1.0f, -0.6961928009986877f, -0.5250730514526367f, -0.39491748809814453f,
    -0.28444138169288635f, -0.18477343022823334f, -0.09105003625154495f, 0.0f,
    0.07958029955625534f, 0.16093020141124725f, 0.24611230194568634f,
    0.33791524171829224f, 0.44070982933044434f, 0.5626170039176941f,
    0.7229568362236023f, 1.0f};

// ---------------- PTX helpers (all base-sm_103 legal) ----------------
DI uint32_t smem_u32(const void* p) {
    return (uint32_t)__cvta_generic_to_shared(p);
}
DI void cp_async16(uint32_t dst, const void* src) {
    asm volatile("cp.async.cg.shared.global [%0], [%1], 16;\n" :: "r"(dst), "l"(src));
}
DI void cp_async_commit() { asm volatile("cp.async.commit_group;\n" ::: "memory"); }
template <int N>
DI void cp_async_wait() { asm volatile("cp.async.wait_group %0;\n" :: "n"(N) : "memory"); }

DI void ldmatrix_x4(uint32_t& r0, uint32_t& r1, uint32_t& r2, uint32_t& r3, uint32_t addr) {
    asm volatile("ldmatrix.sync.aligned.m8n8.x4.shared.b16 {%0,%1,%2,%3}, [%4];"
                 : "=r"(r0), "=r"(r1), "=r"(r2), "=r"(r3) : "r"(addr));
}
DI void mma_16816(float& d0, float& d1, float& d2, float& d3,
                  uint32_t a0, uint32_t a1, uint32_t a2, uint32_t a3,
                  uint32_t b0, uint32_t b1) {
    asm volatile(
        "mma.sync.aligned.m16n8k16.row.col.f32.f16.f16.f32 "
        "{%0,%1,%2,%3}, {%4,%5,%6,%7}, {%8,%9}, {%0,%1,%2,%3};"
        : "+f"(d0), "+f"(d1), "+f"(d2), "+f"(d3)
        : "r"(a0), "r"(a1), "r"(a2), "r"(a3), "r"(b0), "r"(b1));
}

// ---------------- kernel 1: dequant qweight -> g_W[n][k] fp16 ----------------
__global__ void __launch_bounds__(256) dequant_kernel(const int* __restrict__ qw,
                                                      const float* __restrict__ scales) {
    int gid = blockIdx.x * 256 + threadIdx.x;   // over (K/8)*N = 2,097,152
    int r = gid >> 12;                          // qweight row (k = r*8 + j)
    int n = gid & (N_TOTAL - 1);
    uint32_t q = (uint32_t)qw[gid];
    float s = scales[(r >> 4) * N_TOTAL + n];   // group = (r*8)/128 = r/16
    uint4 pack;
    __half* h = reinterpret_cast<__half*>(&pack);
#pragma unroll
    for (int j = 0; j < 8; j++)
        h[j] = __float2half_rn(c_nf4[(q >> (4 * j)) & 15] * s);
    *reinterpret_cast<uint4*>(&g_W[(size_t)n * K_TOTAL + (size_t)r * 8]) = pack;
}

// ---------------- kernel 2: x fp32 -> g_X fp16 ----------------
__global__ void __launch_bounds__(256) xconv_kernel(const float* __restrict__ x) {
    size_t gid = (size_t)blockIdx.x * 256 + threadIdx.x;  // over M*K/8
    const float4* src = reinterpret_cast<const float4*>(x) + gid * 2;
    float4 a = src[0];
    float4 b = src[1];
    uint4 pack;
    __half* h = reinterpret_cast<__half*>(&pack);
    h[0] = __float2half_rn(a.x); h[1] = __float2half_rn(a.y);
    h[2] = __float2half_rn(a.z); h[3] = __float2half_rn(a.w);
    h[4] = __float2half_rn(b.x); h[5] = __float2half_rn(b.y);
    h[6] = __float2half_rn(b.z); h[7] = __float2half_rn(b.w);
    *reinterpret_cast<uint4*>(&g_X[gid * 8]) = pack;
}

// ---------------- kernel 3: HMMA fp16 GEMM + bias ----------------
// CTA 128x256, 4-stage cp.async ring (prefetch distance 3), 8 warps 2(M)x4(N),
// warp tile 64x64, fragment double-buffer across the 4 K-steps per chunk.
__global__ void __launch_bounds__(256, 1) gemm_kernel(const float* __restrict__ bias,
                                                      float* __restrict__ out) {
    extern __shared__ char dyn_smem[];
    const int tid = threadIdx.x;
    const int wid = tid >> 5;
    const int lid = tid & 31;
    const int warp_m = wid & 1;    // 0..1
    const int warp_n = wid >> 1;   // 0..3
    const int n_tile = blockIdx.x;
    const int m_tile = blockIdx.y;

    uint32_t smem_base = (smem_u32(dyn_smem) + 127u) & ~127u;

    const char* gA = reinterpret_cast<const char*>(g_X) +
                     (size_t)(m_tile * TILE_M) * (K_TOTAL * 2);
    const char* gB = reinterpret_cast<const char*>(g_W) +
                     (size_t)(n_tile * TILE_N) * (K_TOTAL * 2);

    // ---- cp.async mapping: 16B granules, 8 per 128B row ----
    const int gcol = tid & 7;          // chunk 0..7 within row
    const int grow = tid >> 3;         // 0..31
    const uint32_t dst_chunk = (uint32_t)(gcol ^ (grow & 7)) << 4;  // swizzled slot

    auto load_stage = [&](int buf, int c) {
        const uint32_t sA = smem_base + buf * STAGE_BYTES;
        const uint32_t sB = sA + A_BYTES;
        const size_t koff = (size_t)c * 128 + gcol * 16;
#pragma unroll
        for (int j = 0; j < 4; j++) {           // A: 128 rows
            int row = grow + 32 * j;
            cp_async16(sA + row * 128 + dst_chunk,
                       gA + (size_t)row * (K_TOTAL * 2) + koff);
        }
#pragma unroll
        for (int j = 0; j < 8; j++) {           // B: 256 rows
            int row = grow + 32 * j;
            cp_async16(sB + row * 128 + dst_chunk,
                       gB + (size_t)row * (K_TOTAL * 2) + koff);
        }
    };

    // prologue: 3 stages in flight (prefetch distance 3)
    load_stage(0, 0); cp_async_commit();
    load_stage(1, 1); cp_async_commit();
    load_stage(2, 2); cp_async_commit();

    // ---- ldmatrix lane addressing (SW128: chunk' = chunk ^ (row&7)) ----
    const int lrow = lid & 15;                     // row within 16-row group
    const uint32_t lchunk = (uint32_t)(lid >> 4);  // 0/1: k-halves
    const uint32_t lxor = (uint32_t)(lid & 7);
    const uint32_t rowA = (uint32_t)(warp_m * 64 + lrow) * 128;
    const uint32_t rowB = (uint32_t)(warp_n * 64 + lrow) * 128;

    float acc[4][8][4];
#pragma unroll
    for (int mi = 0; mi < 4; mi++)
#pragma unroll
        for (int ni = 0; ni < 8; ni++)
#pragma unroll
            for (int v = 0; v < 4; v++) acc[mi][ni][v] = 0.0f;

    uint32_t a[2][4][4], b[2][4][4];

    auto load_frags = [&](int slot, uint32_t sA, uint32_t sB, int ks) {
        const uint32_t csw = (((uint32_t)(2 * ks) + lchunk) ^ lxor) << 4;
#pragma unroll
        for (int mi = 0; mi < 4; mi++)
            ldmatrix_x4(a[slot][mi][0], a[slot][mi][1], a[slot][mi][2], a[slot][mi][3],
                        sA + rowA + mi * 16 * 128 + csw);
#pragma unroll
        for (int nj = 0; nj < 4; nj++)
            ldmatrix_x4(b[slot][nj][0], b[slot][nj][1], b[slot][nj][2], b[slot][nj][3],
                        sB + rowB + nj * 16 * 128 + csw);
    };

    for (int c = 0; c < NUM_CHUNKS; c++) {
        // ledger: pending groups = {c, c+1, c+2}; retire c
        cp_async_wait<2>();
        __syncthreads();      // stage c visible to all warps; all warps done with
                              // buf (c+3)%4 (they last read it as stage c-1)

        const int nc = c + STAGES - 1;
        if (nc < NUM_CHUNKS) load_stage(nc % STAGES, nc);
        cp_async_commit();    // unconditional: empty tail groups keep ledger exact

        const uint32_t sA = smem_base + (c % STAGES) * STAGE_BYTES;
        const uint32_t sB = sA + A_BYTES;

        load_frags(0, sA, sB, 0);
#pragma unroll
        for (int ks = 0; ks < 4; ks++) {
            const int cur = ks & 1;
            if (ks < 3) load_frags(cur ^ 1, sA, sB, ks + 1);  // prefetch next K-step
#pragma unroll
            for (int mi = 0; mi < 4; mi++) {
#pragma unroll
                for (int nj = 0; nj < 4; nj++) {
                    mma_16816(acc[mi][2 * nj][0], acc[mi][2 * nj][1],
                              acc[mi][2 * nj][2], acc[mi][2 * nj][3],
                              a[cur][mi][0], a[cur][mi][1], a[cur][mi][2], a[cur][mi][3],
                              b[cur][nj][0], b[cur][nj][2]);
                    mma_16816(acc[mi][2 * nj + 1][0], acc[mi][2 * nj + 1][1],
                              acc[mi][2 * nj + 1][2], acc[mi][2 * nj + 1][3],
                              a[cur][mi][0], a[cur][mi][1], a[cur][mi][2], a[cur][mi][3],
                              b[cur][nj][1], b[cur][nj][3]);
                }
            }
        }
    }

    // ---- epilogue: add bias, write fp32 out ----
    const int qr = lid >> 2;          // 0..7
    const int qc = (lid & 3) * 2;
    const int m_base = m_tile * TILE_M + warp_m * 64;
    const int n_base = n_tile * TILE_N + warp_n * 64;

#pragma unroll
    for (int ni = 0; ni < 8; ni++) {
        const int col = n_base + ni * 8 + qc;
        const float2 bv = *reinterpret_cast<const float2*>(bias + col);
#pragma unroll
        for (int mi = 0; mi < 4; mi++) {
            const int r0 = m_base + mi * 16 + qr;
            float2 v0, v1;
            v0.x = acc[mi][ni][0] + bv.x;
            v0.y = acc[mi][ni][1] + bv.y;
            v1.x = acc[mi][ni][2] + bv.x;
            v1.y = acc[mi][ni][3] + bv.y;
            *reinterpret_cast<float2*>(out + (size_t)r0 * N_TOTAL + col) = v0;
            *reinterpret_cast<float2*>(out + (size_t)(r0 + 8) * N_TOTAL + col) = v1;
        }
    }
}

// ---------------- launch ----------------
extern "C" void kernel_launch(void* const* d_in, const int* in_sizes, int n_in,
                              void* d_out, int out_size) {
    const float* x      = (const float*)d_in[0];
    const float* scales = (const float*)d_in[1];
    const float* bias   = (const float*)d_in[2];
    const int*   qw     = (const int*)d_in[3];
    float* out = (float*)d_out;

    cudaFuncSetAttribute(gemm_kernel,
                         cudaFuncAttributeMaxDynamicSharedMemorySize, SMEM_ALLOC);

    dequant_kernel<<<(K_TOTAL / 8) * N_TOTAL / 256, 256>>>(qw, scales);
    xconv_kernel<<<(int)((size_t)M_TOTAL * K_TOTAL / 8 / 256), 256>>>(x);

    dim3 grid(N_TOTAL / TILE_N, M_TOTAL / TILE_M);   // 16 x 64
    gemm_kernel<<<grid, 256, SMEM_ALLOC>>>(bias, out);
}

// round 16
// speedup vs baseline: 1.0622x; 1.0469x over previous
#include <cuda_runtime.h>
#include <cuda_fp16.h>
#include <cstdint>

#define DI __device__ __forceinline__

// ---------------- problem constants ----------------
static constexpr int M_TOTAL = 8192;
static constexpr int N_TOTAL = 4096;
static constexpr int K_TOTAL = 4096;

static constexpr int TILE_M = 128;
static constexpr int TILE_N = 128;                    // halved: 2 CTAs/SM
static constexpr int TILE_K = 64;                     // 64 fp16 = 128B rows
static constexpr int NUM_CHUNKS = K_TOTAL / TILE_K;   // 64
static constexpr int STAGES = 3;                      // ring, prefetch distance 2

static constexpr int A_BYTES = TILE_M * 128;          // 16 KB
static constexpr int B_BYTES = TILE_N * 128;          // 16 KB
static constexpr int STAGE_BYTES = A_BYTES + B_BYTES; // 32 KB
static constexpr int SMEM_ALLOC = STAGES * STAGE_BYTES + 256;   // ~96 KB -> 2 CTAs/SM

// ---------------- scratch (no cudaMalloc allowed) ----------------
__device__ __align__(16) __half g_W[(size_t)N_TOTAL * K_TOTAL]; // [n][k] K-major, 32 MB
__device__ __align__(16) __half g_X[(size_t)M_TOTAL * K_TOTAL]; // [m][k] K-major, 64 MB

__device__ const float c_nf4[16] = {
    -1.0f, -0.6961928009986877f, -0.5250730514526367f, -0.39491748809814453f,
    -0.28444138169288635f, -0.18477343022823334f, -0.09105003625154495f, 0.0f,
    0.07958029955625534f, 0.16093020141124725f, 0.24611230194568634f,
    0.33791524171829224f, 0.44070982933044434f, 0.5626170039176941f,
    0.7229568362236023f, 1.0f};

// ---------------- PTX helpers (all base-sm_103 legal) ----------------
DI uint32_t smem_u32(const void* p) {
    return (uint32_t)__cvta_generic_to_shared(p);
}
DI void cp_async16(uint32_t dst, const void* src) {
    asm volatile("cp.async.cg.shared.global [%0], [%1], 16;\n" :: "r"(dst), "l"(src));
}
DI void cp_async_commit() { asm volatile("cp.async.commit_group;\n" ::: "memory"); }
template <int N>
DI void cp_async_wait() { asm volatile("cp.async.wait_group %0;\n" :: "n"(N) : "memory"); }

DI void ldmatrix_x4(uint32_t& r0, uint32_t& r1, uint32_t& r2, uint32_t& r3, uint32_t addr) {
    asm volatile("ldmatrix.sync.aligned.m8n8.x4.shared.b16 {%0,%1,%2,%3}, [%4];"
                 : "=r"(r0), "=r"(r1), "=r"(r2), "=r"(r3) : "r"(addr));
}
DI void mma_16816(float& d0, float& d1, float& d2, float& d3,
                  uint32_t a0, uint32_t a1, uint32_t a2, uint32_t a3,
                  uint32_t b0, uint32_t b1) {
    asm volatile(
        "mma.sync.aligned.m16n8k16.row.col.f32.f16.f16.f32 "
        "{%0,%1,%2,%3}, {%4,%5,%6,%7}, {%8,%9}, {%0,%1,%2,%3};"
        : "+f"(d0), "+f"(d1), "+f"(d2), "+f"(d3)
        : "r"(a0), "r"(a1), "r"(a2), "r"(a3), "r"(b0), "r"(b1));
}

// ---------------- kernel 1: dequant qweight -> g_W[n][k] fp16 ----------------
__global__ void __launch_bounds__(256) dequant_kernel(const int* __restrict__ qw,
                                                      const float* __restrict__ scales) {
    int gid = blockIdx.x * 256 + threadIdx.x;   // over (K/8)*N = 2,097,152
    int r = gid >> 12;                          // qweight row (k = r*8 + j)
    int n = gid & (N_TOTAL - 1);
    uint32_t q = (uint32_t)qw[gid];
    float s = scales[(r >> 4) * N_TOTAL + n];   // group = (r*8)/128 = r/16
    uint4 pack;
    __half* h = reinterpret_cast<__half*>(&pack);
#pragma unroll
    for (int j = 0; j < 8; j++)
        h[j] = __float2half_rn(c_nf4[(q >> (4 * j)) & 15] * s);
    *reinterpret_cast<uint4*>(&g_W[(size_t)n * K_TOTAL + (size_t)r * 8]) = pack;
}

// ---------------- kernel 2: x fp32 -> g_X fp16 ----------------
__global__ void __launch_bounds__(256) xconv_kernel(const float* __restrict__ x) {
    size_t gid = (size_t)blockIdx.x * 256 + threadIdx.x;  // over M*K/8
    const float4* src = reinterpret_cast<const float4*>(x) + gid * 2;
    float4 a = src[0];
    float4 b = src[1];
    uint4 pack;
    __half* h = reinterpret_cast<__half*>(&pack);
    h[0] = __float2half_rn(a.x); h[1] = __float2half_rn(a.y);
    h[2] = __float2half_rn(a.z); h[3] = __float2half_rn(a.w);
    h[4] = __float2half_rn(b.x); h[5] = __float2half_rn(b.y);
    h[6] = __float2half_rn(b.z); h[7] = __float2half_rn(b.w);
    *reinterpret_cast<uint4*>(&g_X[gid * 8]) = pack;
}

// ---------------- kernel 3: HMMA fp16 GEMM + bias ----------------
// CTA 128x128, 4 warps (2Mx2N), warp tile 64x64, 3-stage cp.async ring,
// 96KB smem + ~215 regs -> 2 CTAs/SM so barrier stalls of one CTA are
// covered by the co-resident CTA's issue stream.
__global__ void __launch_bounds__(128, 2) gemm_kernel(const float* __restrict__ bias,
                                                      float* __restrict__ out) {
    extern __shared__ char dyn_smem[];
    const int tid = threadIdx.x;
    const int wid = tid >> 5;
    const int lid = tid & 31;
    const int warp_m = wid & 1;    // 0..1
    const int warp_n = wid >> 1;   // 0..1
    const int n_tile = blockIdx.x;
    const int m_tile = blockIdx.y;

    uint32_t smem_base = (smem_u32(dyn_smem) + 127u) & ~127u;

    const char* gA = reinterpret_cast<const char*>(g_X) +
                     (size_t)(m_tile * TILE_M) * (K_TOTAL * 2);
    const char* gB = reinterpret_cast<const char*>(g_W) +
                     (size_t)(n_tile * TILE_N) * (K_TOTAL * 2);

    // ---- cp.async mapping: 16B granules, 8 per 128B row, 128 threads ----
    const int gcol = tid & 7;          // chunk 0..7 within row
    const int grow = tid >> 3;         // 0..15
    const uint32_t dst_chunk = (uint32_t)(gcol ^ (grow & 7)) << 4;  // swizzled slot

    auto load_stage = [&](int buf, int c) {
        const uint32_t sA = smem_base + buf * STAGE_BYTES;
        const uint32_t sB = sA + A_BYTES;
        const size_t koff = (size_t)c * 128 + gcol * 16;
#pragma unroll
        for (int j = 0; j < 8; j++) {           // A: 128 rows, 16-row stride
            int row = grow + 16 * j;
            cp_async16(sA + row * 128 + dst_chunk,
                       gA + (size_t)row * (K_TOTAL * 2) + koff);
        }
#pragma unroll
        for (int j = 0; j < 8; j++) {           // B: 128 rows
            int row = grow + 16 * j;
            cp_async16(sB + row * 128 + dst_chunk,
                       gB + (size_t)row * (K_TOTAL * 2) + koff);
        }
    };

    // prologue: 2 stages in flight (prefetch distance 2)
    load_stage(0, 0); cp_async_commit();
    load_stage(1, 1); cp_async_commit();

    // ---- ldmatrix lane addressing (SW128: chunk' = chunk ^ (row&7)) ----
    const int lrow = lid & 15;                     // row within 16-row group
    const uint32_t lchunk = (uint32_t)(lid >> 4);  // 0/1: k-halves
    const uint32_t lxor = (uint32_t)(lid & 7);
    const uint32_t rowA = (uint32_t)(warp_m * 64 + lrow) * 128;
    const uint32_t rowB = (uint32_t)(warp_n * 64 + lrow) * 128;

    float acc[4][8][4];
#pragma unroll
    for (int mi = 0; mi < 4; mi++)
#pragma unroll
        for (int ni = 0; ni < 8; ni++)
#pragma unroll
            for (int v = 0; v < 4; v++) acc[mi][ni][v] = 0.0f;

    uint32_t a[2][4][4], b[2][4][4];

    auto load_frags = [&](int slot, uint32_t sA, uint32_t sB, int ks) {
        const uint32_t csw = (((uint32_t)(2 * ks) + lchunk) ^ lxor) << 4;
#pragma unroll
        for (int mi = 0; mi < 4; mi++)
            ldmatrix_x4(a[slot][mi][0], a[slot][mi][1], a[slot][mi][2], a[slot][mi][3],
                        sA + rowA + mi * 16 * 128 + csw);
#pragma unroll
        for (int nj = 0; nj < 4; nj++)
            ldmatrix_x4(b[slot][nj][0], b[slot][nj][1], b[slot][nj][2], b[slot][nj][3],
                        sB + rowB + nj * 16 * 128 + csw);
    };

    for (int c = 0; c < NUM_CHUNKS; c++) {
        // ledger: pending groups = {c, c+1}; retire c
        cp_async_wait<1>();
        __syncthreads();      // stage c visible; all warps done with buf (c+2)%3
                              // (they last read it as stage c-1)

        const int nc = c + STAGES - 1;            // c+2
        if (nc < NUM_CHUNKS) load_stage(nc % STAGES, nc);
        cp_async_commit();    // unconditional: empty tail groups keep ledger exact

        const uint32_t sA = smem_base + (c % STAGES) * STAGE_BYTES;
        const uint32_t sB = sA + A_BYTES;

        load_frags(0, sA, sB, 0);
#pragma unroll
        for (int ks = 0; ks < 4; ks++) {
            const int cur = ks & 1;
            if (ks < 3) load_frags(cur ^ 1, sA, sB, ks + 1);  // prefetch next K-step
#pragma unroll
            for (int mi = 0; mi < 4; mi++) {
#pragma unroll
                for (int nj = 0; nj < 4; nj++) {
                    mma_16816(acc[mi][2 * nj][0], acc[mi][2 * nj][1],
                              acc[mi][2 * nj][2], acc[mi][2 * nj][3],
                              a[cur][mi][0], a[cur][mi][1], a[cur][mi][2], a[cur][mi][3],
                              b[cur][nj][0], b[cur][nj][2]);
                    mma_16816(acc[mi][2 * nj + 1][0], acc[mi][2 * nj + 1][1],
                              acc[mi][2 * nj + 1][2], acc[mi][2 * nj + 1][3],
                              a[cur][mi][0], a[cur][mi][1], a[cur][mi][2], a[cur][mi][3],
                              b[cur][nj][1], b[cur][nj][3]);
                }
            }
        }
    }

    // ---- epilogue: add bias, write fp32 out ----
    const int qr = lid >> 2;          // 0..7
    const int qc = (lid & 3) * 2;
    const int m_base = m_tile * TILE_M + warp_m * 64;
    const int n_base = n_tile * TILE_N + warp_n * 64;

#pragma unroll
    for (int ni = 0; ni < 8; ni++) {
        const int col = n_base + ni * 8 + qc;
        const float2 bv = *reinterpret_cast<const float2*>(bias + col);
#pragma unroll
        for (int mi = 0; mi < 4; mi++) {
            const int r0 = m_base + mi * 16 + qr;
            float2 v0, v1;
            v0.x = acc[mi][ni][0] + bv.x;
            v0.y = acc[mi][ni][1] + bv.y;
            v1.x = acc[mi][ni][2] + bv.x;
            v1.y = acc[mi][ni][3] + bv.y;
            *reinterpret_cast<float2*>(out + (size_t)r0 * N_TOTAL + col) = v0;
            *reinterpret_cast<float2*>(out + (size_t)(r0 + 8) * N_TOTAL + col) = v1;
        }
    }
}

// ---------------- launch ----------------
extern "C" void kernel_launch(void* const* d_in, const int* in_sizes, int n_in,
                              void* d_out, int out_size) {
    const float* x      = (const float*)d_in[0];
    const float* scales = (const float*)d_in[1];
    const float* bias   = (const float*)d_in[2];
    const int*   qw     = (const int*)d_in[3];
    float* out = (float*)d_out;

    cudaFuncSetAttribute(gemm_kernel,
                         cudaFuncAttributeMaxDynamicSharedMemorySize, SMEM_ALLOC);

    dequant_kernel<<<(K_TOTAL / 8) * N_TOTAL / 256, 256>>>(qw, scales);
    xconv_kernel<<<(int)((size_t)M_TOTAL * K_TOTAL / 8 / 256), 256>>>(x);

    dim3 grid(N_TOTAL / TILE_N, M_TOTAL / TILE_M);   // 32 x 64
    gemm_kernel<<<grid, 128, SMEM_ALLOC>>>(bias, out);
}